// round 16
// baseline (speedup 1.0000x reference)
#include <cuda_runtime.h>
#include <cuda_fp16.h>
#include <cstdint>
#include <math.h>

#define Bc 4
#define Sc 1024
#define Dc 1024
#define Hc 8
#define DKc 128
#define FFc 4096
#define TOK (Bc*Sc)
typedef __half h16;
#define QSCALE 0.1275160352896431f

// ---- scratch ----
__device__ __align__(16) h16 g_xn [TOK*Dc];
__device__ __align__(16) h16 g_xn2[TOK*Dc];
__device__ __align__(16) h16 g_wqkv[(size_t)3*Dc*Dc];
__device__ __align__(16) float g_bqkv[3*Dc];
__device__ __align__(16) h16 g_W1T[(size_t)FFc*Dc];
__device__ __align__(16) h16 g_W2T[(size_t)Dc*FFc];
__device__ __align__(16) h16 g_qkv[(size_t)3*TOK*Dc];
__device__ __align__(16) float g_x1[TOK*Dc];
__device__ __align__(16) h16 g_ff[(size_t)TOK*FFc];

// ---- helpers ----
__device__ __forceinline__ uint32_t smem_u32(const void* p) {
    uint32_t a;
    asm("{ .reg .u64 t; cvta.to.shared.u64 t, %1; cvt.u32.u64 %0, t; }" : "=r"(a) : "l"(p));
    return a;
}
#define CP16(dst, src) asm volatile("cp.async.cg.shared.global [%0], [%1], 16;" :: "r"(dst), "l"(src))
#define CP_COMMIT()    asm volatile("cp.async.commit_group;" ::: "memory")
#define CP_WAIT1()     asm volatile("cp.async.wait_group 1;" ::: "memory")
#define CP_WAIT0()     asm volatile("cp.async.wait_group 0;" ::: "memory")

__device__ __forceinline__ void ldsm_x4(uint32_t& a0, uint32_t& a1, uint32_t& a2, uint32_t& a3, uint32_t addr) {
    asm volatile("ldmatrix.sync.aligned.m8n8.x4.shared.b16 {%0,%1,%2,%3}, [%4];"
                 : "=r"(a0), "=r"(a1), "=r"(a2), "=r"(a3) : "r"(addr));
}
__device__ __forceinline__ void ldsm_x4t(uint32_t& a0, uint32_t& a1, uint32_t& a2, uint32_t& a3, uint32_t addr) {
    asm volatile("ldmatrix.sync.aligned.m8n8.x4.trans.shared.b16 {%0,%1,%2,%3}, [%4];"
                 : "=r"(a0), "=r"(a1), "=r"(a2), "=r"(a3) : "r"(addr));
}
__device__ __forceinline__ void mma16816(float* c, uint32_t a0, uint32_t a1, uint32_t a2, uint32_t a3,
                                         uint32_t b0, uint32_t b1) {
    asm volatile("mma.sync.aligned.m16n8k16.row.col.f32.f16.f16.f32 "
                 "{%0,%1,%2,%3},{%4,%5,%6,%7},{%8,%9},{%0,%1,%2,%3};"
                 : "+f"(c[0]), "+f"(c[1]), "+f"(c[2]), "+f"(c[3])
                 : "r"(a0), "r"(a1), "r"(a2), "r"(a3), "r"(b0), "r"(b1));
}
__device__ __forceinline__ uint32_t h2exp2_u(uint32_t x) {
    uint32_t r;
    asm("ex2.approx.f16x2 %0, %1;" : "=r"(r) : "r"(x));
    return r;
}
__device__ __forceinline__ float gelu_exact(float v) {
    return 0.5f * v * (1.0f + erff(v * 0.70710678118654752f));
}

// ---- HMMA fp16 GEMM: 128x128 CTA tile, K-chunk 64, 3-stage cp.async, 2 CTA/SM ----
#define STAGE_B 32768
#define GSMEM   (3*STAGE_B)

template<int ACT, int OUTMODE>
__global__ void __launch_bounds__(256, 2)
gemm_hmma(const h16* __restrict__ Ah, const h16* __restrict__ Bh,
          const float* __restrict__ bias, const float* __restrict__ resid,
          float* __restrict__ C, h16* __restrict__ Ch,
          int K, int lda, int ldb, int ldc,
          long long sA0, long long sA1, long long sB0, long long sB1,
          long long sC0, long long sC1, int innerB, float alpha, long long biasStride)
{
    extern __shared__ char smem[];
    const uint32_t smb = smem_u32(smem);
    const int tid = threadIdx.x, lane = tid & 31, wid = tid >> 5;
    const int z = blockIdx.z, zo = z / innerB, zi = z - zo * innerB;
    const long long aoff = zo * sA0 + zi * sA1;
    const long long boff = zo * sB0 + zi * sB1;
    const long long coff = zo * sC0 + zi * sC1;
    if (bias) bias += (long long)z * biasStride;
    const int m0 = blockIdx.y * 128, n0 = blockIdx.x * 128;
    const int wm = (wid & 1) * 64, wn = (wid >> 1) * 32;

    const int lrow = tid >> 3;
    const int cch  = tid & 7;

    float acc[4][4][4];
    #pragma unroll
    for (int i = 0; i < 4; i++)
        #pragma unroll
        for (int j = 0; j < 4; j++)
            #pragma unroll
            for (int t = 0; t < 4; t++) acc[i][j][t] = 0.f;

    const int nck = K >> 6;

    auto load_chunk = [&](int kk, int s) {
        const int k0 = kk << 6;
        const uint32_t st = smb + s * STAGE_B;
        #pragma unroll
        for (int rep = 0; rep < 4; rep++) {
            const int r = lrow + rep * 32;
            const uint32_t so = r * 128 + ((cch ^ (r & 7)) << 4);
            CP16(st + so,         Ah + (size_t)aoff + (size_t)(m0 + r) * lda + k0 + cch * 8);
            CP16(st + 16384 + so, Bh + (size_t)boff + (size_t)(n0 + r) * ldb + k0 + cch * 8);
        }
        CP_COMMIT();
    };

    load_chunk(0, 0);
    load_chunk(1, 1);

    for (int kk = 0; kk < nck; kk++) {
        CP_WAIT1();
        __syncthreads();
        if (kk + 2 < nck) load_chunk(kk + 2, (kk + 2) % 3);
        else CP_COMMIT();

        const uint32_t st = smb + (kk % 3) * STAGE_B;
        #pragma unroll
        for (int ks = 0; ks < 4; ks++) {
            uint32_t ah[4][4], bh[4][2];
            #pragma unroll
            for (int mf = 0; mf < 4; mf++) {
                const int r = wm + mf * 16 + (lane & 15);
                const int ch = ks * 2 + (lane >> 4);
                ldsm_x4(ah[mf][0], ah[mf][1], ah[mf][2], ah[mf][3],
                        st + r * 128 + ((ch ^ (r & 7)) << 4));
            }
            #pragma unroll
            for (int nf2 = 0; nf2 < 2; nf2++) {
                const int r = wn + nf2 * 16 + ((lane >> 4) & 1) * 8 + (lane & 7);
                const int ch = ks * 2 + ((lane >> 3) & 1);
                ldsm_x4(bh[2*nf2][0], bh[2*nf2][1], bh[2*nf2+1][0], bh[2*nf2+1][1],
                        st + 16384 + r * 128 + ((ch ^ (r & 7)) << 4));
            }
            #pragma unroll
            for (int mf = 0; mf < 4; mf++)
                #pragma unroll
                for (int nf = 0; nf < 4; nf++)
                    mma16816(acc[mf][nf], ah[mf][0], ah[mf][1], ah[mf][2], ah[mf][3], bh[nf][0], bh[nf][1]);
        }
    }

    #pragma unroll
    for (int mf = 0; mf < 4; mf++) {
        const int r0 = m0 + wm + mf * 16 + (lane >> 2);
        const int r1 = r0 + 8;
        #pragma unroll
        for (int nf = 0; nf < 4; nf++) {
            const int col = n0 + wn + nf * 8 + (lane & 3) * 2;
            float b0 = 0.f, b1 = 0.f;
            if (bias) { b0 = __ldg(bias + col); b1 = __ldg(bias + col + 1); }
            float v0 = acc[mf][nf][0] * alpha + b0;
            float v1 = acc[mf][nf][1] * alpha + b1;
            float v2 = acc[mf][nf][2] * alpha + b0;
            float v3 = acc[mf][nf][3] * alpha + b1;
            if (ACT == 1) {
                v0 = gelu_exact(v0); v1 = gelu_exact(v1);
                v2 = gelu_exact(v2); v3 = gelu_exact(v3);
            }
            const size_t i0 = (size_t)coff + (size_t)r0 * ldc + col;
            const size_t i1 = (size_t)coff + (size_t)r1 * ldc + col;
            if (OUTMODE == 0) {
                if (resid) {
                    float2 q0 = *(const float2*)(resid + i0);
                    float2 q1 = *(const float2*)(resid + i1);
                    v0 += q0.x; v1 += q0.y; v2 += q1.x; v3 += q1.y;
                }
                *(float2*)(C + i0) = make_float2(v0, v1);
                *(float2*)(C + i1) = make_float2(v2, v3);
            } else {
                __half2 p0 = __floats2half2_rn(v0, v1);
                __half2 p1 = __floats2half2_rn(v2, v3);
                *(__half2*)(Ch + i0) = p0;
                *(__half2*)(Ch + i1) = p1;
            }
        }
    }
}

// ---- fused flash attention: 64-row KV tiles, 2-stage, 2 CTA/SM ----
// smem: q 32KB | 2 stages x (K 16KB [4 slabs x 64rows x 64B] | V 16KB [64 x 256B rows])
#define FA_STAGE 32768
#define FA_SMEM  (32768 + 2*FA_STAGE)
#define ONE2 0x3C003C00u

__global__ void __launch_bounds__(256, 2)
flash_attn(const h16* __restrict__ qg, const h16* __restrict__ kg,
           const h16* __restrict__ vg, const float* __restrict__ x,
           float* __restrict__ x1)
{
    extern __shared__ char smem[];
    const uint32_t smb = smem_u32(smem);
    const int qt = blockIdx.x, z = blockIdx.y;
    const int b = z >> 3, h = z & 7;
    const int tid = threadIdx.x, lane = tid & 31, wid = tid >> 5;

    const size_t qkbase = (size_t)b * Sc * Dc + (size_t)h * DKc;

    const int row = tid >> 2;      // 0..63
    const int cch = tid & 3;
    const int vrow = tid >> 4;     // 0..15
    const int vch  = tid & 15;

    // q tile 128x128 (4 slabs of 64B rows)
    {
        #pragma unroll
        for (int slab = 0; slab < 4; slab++)
            #pragma unroll
            for (int rep = 0; rep < 2; rep++) {
                const int r = row + rep * 64;
                const uint32_t so = slab * 8192 + r * 64 + ((cch ^ (r & 3)) << 4);
                CP16(smb + so, qg + qkbase + (size_t)(qt * 128 + r) * Dc + slab * 32 + cch * 8);
            }
    }
    auto load_kv = [&](int kt, int st) {
        const uint32_t sb = smb + 32768 + st * FA_STAGE;
        // K: 64 rows, 4 slabs x 64B
        #pragma unroll
        for (int slab = 0; slab < 4; slab++) {
            const int r = row;
            const uint32_t so = slab * 4096 + r * 64 + ((cch ^ (r & 3)) << 4);
            CP16(sb + so, kg + qkbase + (size_t)(kt * 64 + r) * Dc + slab * 32 + cch * 8);
        }
        // V: 64 rows x 256B
        #pragma unroll
        for (int rep = 0; rep < 4; rep++) {
            const int r = vrow + rep * 16;
            const uint32_t so = 16384 + r * 256 + ((vch ^ (r & 15)) << 4);
            CP16(sb + so, vg + qkbase + (size_t)(kt * 64 + r) * Dc + vch * 8);
        }
        CP_COMMIT();
    };
    load_kv(0, 0);

    float acc_o[16][4];
    float acc_l[4] = {0.f, 0.f, 0.f, 0.f};
    #pragma unroll
    for (int nf = 0; nf < 16; nf++)
        #pragma unroll
        for (int t = 0; t < 4; t++) acc_o[nf][t] = 0.f;

    for (int kt = 0; kt < 16; kt++) {
        CP_WAIT0();
        __syncthreads();
        if (kt + 1 < 16) load_kv(kt + 1, (kt + 1) & 1);

        const uint32_t sbk = smb + 32768 + (kt & 1) * FA_STAGE;
        const uint32_t sbv = sbk + 16384;

        // S = q_scaled @ k^T over 64 kv rows (q frags reloaded per kc)
        float s_acc[8][4];
        #pragma unroll
        for (int nf = 0; nf < 8; nf++)
            #pragma unroll
            for (int t = 0; t < 4; t++) s_acc[nf][t] = 0.f;
        #pragma unroll
        for (int kc = 0; kc < 8; kc++) {
            const int slab = kc >> 1, ks = kc & 1;
            uint32_t a0, a1, a2, a3;
            {
                const int r = wid * 16 + (lane & 15);
                const int ch = ks * 2 + (lane >> 4);
                ldsm_x4(a0, a1, a2, a3, smb + slab * 8192 + r * 64 + ((ch ^ (r & 3)) << 4));
            }
            #pragma unroll
            for (int nf2 = 0; nf2 < 4; nf2++) {
                const int r = nf2 * 16 + ((lane >> 4) & 1) * 8 + (lane & 7);
                const int ch = ks * 2 + ((lane >> 3) & 1);
                uint32_t b0, b1, b2, b3;
                ldsm_x4(b0, b1, b2, b3, sbk + slab * 4096 + r * 64 + ((ch ^ (r & 3)) << 4));
                mma16816(s_acc[2*nf2],   a0, a1, a2, a3, b0, b1);
                mma16816(s_acc[2*nf2+1], a0, a1, a2, a3, b2, b3);
            }
        }

        // p = 2^s; rowsum via ones-MMA; acc_o += P @ V
        #pragma unroll
        for (int kc = 0; kc < 4; kc++) {
            __half2 pa0 = __floats2half2_rn(s_acc[2*kc][0],   s_acc[2*kc][1]);
            __half2 pa1 = __floats2half2_rn(s_acc[2*kc][2],   s_acc[2*kc][3]);
            __half2 pa2 = __floats2half2_rn(s_acc[2*kc+1][0], s_acc[2*kc+1][1]);
            __half2 pa3 = __floats2half2_rn(s_acc[2*kc+1][2], s_acc[2*kc+1][3]);
            const uint32_t u0 = h2exp2_u(*(uint32_t*)&pa0);
            const uint32_t u1 = h2exp2_u(*(uint32_t*)&pa1);
            const uint32_t u2 = h2exp2_u(*(uint32_t*)&pa2);
            const uint32_t u3 = h2exp2_u(*(uint32_t*)&pa3);
            mma16816(acc_l, u0, u1, u2, u3, ONE2, ONE2);
            #pragma unroll
            for (int nf2 = 0; nf2 < 8; nf2++) {
                const int r = kc * 16 + ((lane >> 3) & 1) * 8 + (lane & 7);
                const int cb = 2 * nf2 + (lane >> 4);
                uint32_t b0, b1, b2, b3;
                ldsm_x4t(b0, b1, b2, b3, sbv + r * 256 + ((cb ^ (r & 15)) << 4));
                mma16816(acc_o[2*nf2],   u0, u1, u2, u3, b0, b1);
                mma16816(acc_o[2*nf2+1], u0, u1, u2, u3, b2, b3);
            }
        }
    }

    const float inv0 = 1.f / acc_l[0], inv1 = 1.f / acc_l[2];
    const size_t zbase = (size_t)z * Sc * DKc;
    const int gr0 = qt * 128 + wid * 16 + (lane >> 2);
    #pragma unroll
    for (int nf = 0; nf < 16; nf++) {
        const int col = nf * 8 + (lane & 3) * 2;
        const size_t i0 = zbase + (size_t)gr0 * DKc + col;
        const size_t i1 = i0 + 8 * DKc;
        float2 r0 = *(const float2*)(x + i0);
        float2 r1 = *(const float2*)(x + i1);
        *(float2*)(x1 + i0) = make_float2(acc_o[nf][0] * inv0 + r0.x, acc_o[nf][1] * inv0 + r0.y);
        *(float2*)(x1 + i1) = make_float2(acc_o[nf][2] * inv1 + r1.x, acc_o[nf][3] * inv1 + r1.y);
    }
}

// ---- layernorm -> fp16 ----
__global__ void __launch_bounds__(256)
ln_half(const float* __restrict__ x, const float* __restrict__ g,
        const float* __restrict__ b, h16* __restrict__ o)
{
    const long long row = blockIdx.x;
    const int tid = threadIdx.x;
    float4 v = *(const float4*)(x + row * Dc + tid * 4);
    float s = v.x+v.y+v.z+v.w, ss = v.x*v.x+v.y*v.y+v.z*v.z+v.w*v.w;
    __shared__ float shs[8], shq[8];
    #pragma unroll
    for (int o2 = 16; o2; o2 >>= 1) { s += __shfl_xor_sync(~0u,s,o2); ss += __shfl_xor_sync(~0u,ss,o2); }
    if ((tid & 31) == 0) { shs[tid>>5] = s; shq[tid>>5] = ss; }
    __syncthreads();
    float st=0.f, qt=0.f;
    #pragma unroll
    for (int i = 0; i < 8; i++) { st += shs[i]; qt += shq[i]; }
    const float m = st * (1.f/Dc), inv = rsqrtf(qt*(1.f/Dc) - m*m + 1e-5f);
    float4 gv = *(const float4*)(g + tid*4);
    float4 bv = *(const float4*)(b + tid*4);
    __half2 h0 = __floats2half2_rn((v.x-m)*inv*gv.x+bv.x, (v.y-m)*inv*gv.y+bv.y);
    __half2 h1 = __floats2half2_rn((v.z-m)*inv*gv.z+bv.z, (v.w-m)*inv*gv.w+bv.w);
    uint2 pk; pk.x = *(uint32_t*)&h0; pk.y = *(uint32_t*)&h1;
    *(uint2*)(o + row*Dc + tid*4) = pk;
}

// ---- merged weight transpose (Wq scaled by QSCALE) ----
__global__ void __launch_bounds__(256)
transpose_all(const float* __restrict__ Wq, const float* __restrict__ Wk,
              const float* __restrict__ W1, const float* __restrict__ W2,
              h16* __restrict__ oq, h16* __restrict__ ok,
              h16* __restrict__ o1, h16* __restrict__ o2)
{
    __shared__ float t[64][33];
    int bid = blockIdx.x;
    const float* in; h16* out;
    int ldin, ldo, tx_, ty_;
    float sc = 1.0f;
    if (bid < 512)        { int t2 = bid;        in = Wq; out = oq; ldin = Dc;  ldo = Dc;  tx_ = t2 & 31;  ty_ = t2 >> 5; sc = QSCALE; }
    else if (bid < 1024)  { int t2 = bid - 512;  in = Wk; out = ok; ldin = Dc;  ldo = Dc;  tx_ = t2 & 31;  ty_ = t2 >> 5; }
    else if (bid < 3072)  { int t2 = bid - 1024; in = W1; out = o1; ldin = FFc; ldo = Dc;  tx_ = t2 & 127; ty_ = t2 >> 7; }
    else                  { int t2 = bid - 3072; in = W2; out = o2; ldin = Dc;  ldo = FFc; tx_ = t2 & 31;  ty_ = t2 >> 5; }
    const int c0 = tx_ * 32, r0 = ty_ * 64;
    const int tid = threadIdx.x;
    const int lcol = tid & 31, lrow = tid >> 5;
    #pragma unroll
    for (int rep = 0; rep < 8; rep++) {
        const int r = lrow + rep * 8;
        t[r][lcol] = in[(size_t)(r0 + r) * ldin + c0 + lcol];
    }
    __syncthreads();
    const int lane = tid & 31, wrp = tid >> 5;
    #pragma unroll
    for (int pass = 0; pass < 4; pass++) {
        const int c = pass * 8 + wrp;
        __half2 pk = __floats2half2_rn(t[2*lane][c] * sc, t[2*lane+1][c] * sc);
        *(__half2*)(out + (size_t)(c0 + c) * ldo + r0 + 2*lane) = pk;
    }
}

// ---- fold Wv ----
__global__ void __launch_bounds__(256)
fold_wv(const float* __restrict__ Wv, h16* __restrict__ o)
{
    __shared__ float sf[32][33];
    const int k0 = blockIdx.x * 32, nf0 = blockIdx.y * 32;
    const int tx = threadIdx.x, ty = threadIdx.y;
    #pragma unroll
    for (int rep = 0; rep < 4; rep++) {
        const int row = ty + rep * 8;
        const float* src = Wv + (size_t)(k0 + row) * (Hc*Dc) + (size_t)(nf0 + tx) * 8;
        float4 a = *(const float4*)src;
        float4 b = *(const float4*)(src + 4);
        sf[row][tx] = a.x + a.y + a.z + a.w + b.x + b.y + b.z + b.w;
    }
    __syncthreads();
    #pragma unroll
    for (int rep = 0; rep < 4; rep++) {
        const int nf = ty + rep * 8;
        o[(size_t)(nf0 + nf) * Dc + k0 + tx] = __float2half_rn(sf[tx][nf]);
    }
}

// ---- bias prep (bq scaled by QSCALE) ----
__global__ void prep_bias(const float* __restrict__ bq, const float* __restrict__ bk,
                          const float* __restrict__ bv, float* __restrict__ bqkv)
{
    const int i = blockIdx.x * blockDim.x + threadIdx.x;
    bqkv[i] = bq[i] * QSCALE;
    bqkv[Dc + i] = bk[i];
    const float* s = bv + (size_t)i * 8;
    float t = 0.f;
    #pragma unroll
    for (int j = 0; j < 8; j++) t += s[j];
    bqkv[2*Dc + i] = t;
}

#define SYM(p, s) cudaGetSymbolAddress((void**)&p, s)

extern "C" void kernel_launch(void* const* d_in, const int* in_sizes, int n_in,
                              void* d_out, int out_size)
{
    (void)in_sizes; (void)n_in; (void)out_size;
    const float* x   = (const float*)d_in[0];
    const float* g1  = (const float*)d_in[2];
    const float* b1  = (const float*)d_in[3];
    const float* Wq  = (const float*)d_in[4];
    const float* bq  = (const float*)d_in[5];
    const float* Wk  = (const float*)d_in[6];
    const float* bk  = (const float*)d_in[7];
    const float* Wv  = (const float*)d_in[8];
    const float* bv  = (const float*)d_in[9];
    const float* g2  = (const float*)d_in[10];
    const float* b2  = (const float*)d_in[11];
    const float* W1  = (const float*)d_in[12];
    const float* bw1 = (const float*)d_in[13];
    const float* W2  = (const float*)d_in[14];
    const float* bw2 = (const float*)d_in[15];
    float* out = (float*)d_out;

    h16 *xn,*xn2,*wqkv,*w1t,*w2t,*qkv,*ff;
    float *bqkv,*x1;
    SYM(xn,g_xn); SYM(xn2,g_xn2);
    SYM(wqkv,g_wqkv); SYM(bqkv,g_bqkv);
    SYM(w1t,g_W1T); SYM(w2t,g_W2T);
    SYM(qkv,g_qkv);
    SYM(ff,g_ff); SYM(x1,g_x1);

    cudaFuncSetAttribute(gemm_hmma<0,0>, cudaFuncAttributeMaxDynamicSharedMemorySize, GSMEM);
    cudaFuncSetAttribute(gemm_hmma<0,1>, cudaFuncAttributeMaxDynamicSharedMemorySize, GSMEM);
    cudaFuncSetAttribute(gemm_hmma<1,1>, cudaFuncAttributeMaxDynamicSharedMemorySize, GSMEM);
    cudaFuncSetAttribute(flash_attn,     cudaFuncAttributeMaxDynamicSharedMemorySize, FA_SMEM);

    const dim3 tb(32, 8);
    const size_t DD = (size_t)Dc*Dc;

    prep_bias<<<4, 256>>>(bq, bk, bv, bqkv);
    transpose_all<<<5120, 256>>>(Wq, Wk, W1, W2, wqkv, wqkv + DD, w1t, w2t);
    fold_wv<<<dim3(32, 32), tb>>>(Wv, wqkv + 2*DD);

    ln_half<<<TOK, 256>>>(x, g1, b1, xn);

    gemm_hmma<0,1><<<dim3(Dc/128, TOK/128, 3), 256, GSMEM>>>(
        xn, wqkv, bqkv, nullptr, nullptr, qkv,
        Dc, Dc, Dc, Dc,
        0, 0, (long long)DD, 0, (long long)TOK*Dc, 0, 1, 1.0f, (long long)Dc);

    flash_attn<<<dim3(Sc/128, Bc*Hc), 256, FA_SMEM>>>(
        qkv, qkv + (size_t)TOK*Dc, qkv + (size_t)2*TOK*Dc, x, x1);

    ln_half<<<TOK, 256>>>(x1, g2, b2, xn2);

    gemm_hmma<1,1><<<dim3(FFc/128, TOK/128, 1), 256, GSMEM>>>(
        xn2, w1t, bw1, nullptr, nullptr, ff,
        Dc, Dc, Dc, FFc, 0,0,0,0,0,0, 1, 1.0f, 0);

    gemm_hmma<0,0><<<dim3(Dc/128, TOK/128, 1), 256, GSMEM>>>(
        ff, w2t, bw2, x1, out, nullptr,
        FFc, FFc, FFc, Dc, 0,0,0,0,0,0, 1, 1.0f, 0);
}

// round 17
// speedup vs baseline: 1.0210x; 1.0210x over previous
#include <cuda_runtime.h>
#include <cuda_fp16.h>
#include <cstdint>
#include <math.h>

#define Bc 4
#define Sc 1024
#define Dc 1024
#define Hc 8
#define DKc 128
#define FFc 4096
#define TOK (Bc*Sc)
typedef __half h16;
#define QSCALE 0.1275160352896431f

// ---- scratch ----
__device__ __align__(16) h16 g_xn [TOK*Dc];
__device__ __align__(16) h16 g_xn2[TOK*Dc];
__device__ __align__(16) h16 g_wqkv[(size_t)3*Dc*Dc];
__device__ __align__(16) float g_bqkv[3*Dc];
__device__ __align__(16) h16 g_W1T[(size_t)FFc*Dc];
__device__ __align__(16) h16 g_W2T[(size_t)Dc*FFc];
__device__ __align__(16) h16 g_qkv[(size_t)3*TOK*Dc];
__device__ __align__(16) float g_x1[TOK*Dc];
__device__ __align__(16) h16 g_ff[(size_t)TOK*FFc];

// ---- helpers ----
__device__ __forceinline__ uint32_t smem_u32(const void* p) {
    uint32_t a;
    asm("{ .reg .u64 t; cvta.to.shared.u64 t, %1; cvt.u32.u64 %0, t; }" : "=r"(a) : "l"(p));
    return a;
}
#define CP16(dst, src) asm volatile("cp.async.cg.shared.global [%0], [%1], 16;" :: "r"(dst), "l"(src))
#define CP_COMMIT()    asm volatile("cp.async.commit_group;" ::: "memory")
#define CP_WAIT1()     asm volatile("cp.async.wait_group 1;" ::: "memory")

__device__ __forceinline__ void ldsm_x4(uint32_t& a0, uint32_t& a1, uint32_t& a2, uint32_t& a3, uint32_t addr) {
    asm volatile("ldmatrix.sync.aligned.m8n8.x4.shared.b16 {%0,%1,%2,%3}, [%4];"
                 : "=r"(a0), "=r"(a1), "=r"(a2), "=r"(a3) : "r"(addr));
}
__device__ __forceinline__ void ldsm_x4t(uint32_t& a0, uint32_t& a1, uint32_t& a2, uint32_t& a3, uint32_t addr) {
    asm volatile("ldmatrix.sync.aligned.m8n8.x4.trans.shared.b16 {%0,%1,%2,%3}, [%4];"
                 : "=r"(a0), "=r"(a1), "=r"(a2), "=r"(a3) : "r"(addr));
}
__device__ __forceinline__ void mma16816(float* c, uint32_t a0, uint32_t a1, uint32_t a2, uint32_t a3,
                                         uint32_t b0, uint32_t b1) {
    asm volatile("mma.sync.aligned.m16n8k16.row.col.f32.f16.f16.f32 "
                 "{%0,%1,%2,%3},{%4,%5,%6,%7},{%8,%9},{%0,%1,%2,%3};"
                 : "+f"(c[0]), "+f"(c[1]), "+f"(c[2]), "+f"(c[3])
                 : "r"(a0), "r"(a1), "r"(a2), "r"(a3), "r"(b0), "r"(b1));
}
__device__ __forceinline__ uint32_t h2exp2_u(uint32_t x) {
    uint32_t r;
    asm("ex2.approx.f16x2 %0, %1;" : "=r"(r) : "r"(x));
    return r;
}
__device__ __forceinline__ float gelu_exact(float v) {
    return 0.5f * v * (1.0f + erff(v * 0.70710678118654752f));
}

// ---- HMMA fp16 GEMM: 128x128 CTA tile, K-chunk 64, 3-stage cp.async, 2 CTA/SM ----
#define STAGE_B 32768
#define GSMEM   (3*STAGE_B)

template<int ACT, int OUTMODE>
__global__ void __launch_bounds__(256, 2)
gemm_hmma(const h16* __restrict__ Ah, const h16* __restrict__ Bh,
          const float* __restrict__ bias, const float* __restrict__ resid,
          float* __restrict__ C, h16* __restrict__ Ch,
          int K, int lda, int ldb, int ldc,
          long long sA0, long long sA1, long long sB0, long long sB1,
          long long sC0, long long sC1, int innerB, float alpha, long long biasStride)
{
    extern __shared__ char smem[];
    const uint32_t smb = smem_u32(smem);
    const int tid = threadIdx.x, lane = tid & 31, wid = tid >> 5;
    const int z = blockIdx.z, zo = z / innerB, zi = z - zo * innerB;
    const long long aoff = zo * sA0 + zi * sA1;
    const long long boff = zo * sB0 + zi * sB1;
    const long long coff = zo * sC0 + zi * sC1;
    if (bias) bias += (long long)z * biasStride;
    const int m0 = blockIdx.y * 128, n0 = blockIdx.x * 128;
    const int wm = (wid & 1) * 64, wn = (wid >> 1) * 32;

    const int lrow = tid >> 3;
    const int cch  = tid & 7;

    float acc[4][4][4];
    #pragma unroll
    for (int i = 0; i < 4; i++)
        #pragma unroll
        for (int j = 0; j < 4; j++)
            #pragma unroll
            for (int t = 0; t < 4; t++) acc[i][j][t] = 0.f;

    const int nck = K >> 6;

    auto load_chunk = [&](int kk, int s) {
        const int k0 = kk << 6;
        const uint32_t st = smb + s * STAGE_B;
        #pragma unroll
        for (int rep = 0; rep < 4; rep++) {
            const int r = lrow + rep * 32;
            const uint32_t so = r * 128 + ((cch ^ (r & 7)) << 4);
            CP16(st + so,         Ah + (size_t)aoff + (size_t)(m0 + r) * lda + k0 + cch * 8);
            CP16(st + 16384 + so, Bh + (size_t)boff + (size_t)(n0 + r) * ldb + k0 + cch * 8);
        }
        CP_COMMIT();
    };

    load_chunk(0, 0);
    load_chunk(1, 1);

    for (int kk = 0; kk < nck; kk++) {
        CP_WAIT1();
        __syncthreads();
        if (kk + 2 < nck) load_chunk(kk + 2, (kk + 2) % 3);
        else CP_COMMIT();

        const uint32_t st = smb + (kk % 3) * STAGE_B;
        #pragma unroll
        for (int ks = 0; ks < 4; ks++) {
            uint32_t ah[4][4], bh[4][2];
            #pragma unroll
            for (int mf = 0; mf < 4; mf++) {
                const int r = wm + mf * 16 + (lane & 15);
                const int ch = ks * 2 + (lane >> 4);
                ldsm_x4(ah[mf][0], ah[mf][1], ah[mf][2], ah[mf][3],
                        st + r * 128 + ((ch ^ (r & 7)) << 4));
            }
            #pragma unroll
            for (int nf2 = 0; nf2 < 2; nf2++) {
                const int r = wn + nf2 * 16 + ((lane >> 4) & 1) * 8 + (lane & 7);
                const int ch = ks * 2 + ((lane >> 3) & 1);
                ldsm_x4(bh[2*nf2][0], bh[2*nf2][1], bh[2*nf2+1][0], bh[2*nf2+1][1],
                        st + 16384 + r * 128 + ((ch ^ (r & 7)) << 4));
            }
            #pragma unroll
            for (int mf = 0; mf < 4; mf++)
                #pragma unroll
                for (int nf = 0; nf < 4; nf++)
                    mma16816(acc[mf][nf], ah[mf][0], ah[mf][1], ah[mf][2], ah[mf][3], bh[nf][0], bh[nf][1]);
        }
    }

    #pragma unroll
    for (int mf = 0; mf < 4; mf++) {
        const int r0 = m0 + wm + mf * 16 + (lane >> 2);
        const int r1 = r0 + 8;
        #pragma unroll
        for (int nf = 0; nf < 4; nf++) {
            const int col = n0 + wn + nf * 8 + (lane & 3) * 2;
            float b0 = 0.f, b1 = 0.f;
            if (bias) { b0 = __ldg(bias + col); b1 = __ldg(bias + col + 1); }
            float v0 = acc[mf][nf][0] * alpha + b0;
            float v1 = acc[mf][nf][1] * alpha + b1;
            float v2 = acc[mf][nf][2] * alpha + b0;
            float v3 = acc[mf][nf][3] * alpha + b1;
            if (ACT == 1) {
                v0 = gelu_exact(v0); v1 = gelu_exact(v1);
                v2 = gelu_exact(v2); v3 = gelu_exact(v3);
            }
            const size_t i0 = (size_t)coff + (size_t)r0 * ldc + col;
            const size_t i1 = (size_t)coff + (size_t)r1 * ldc + col;
            if (OUTMODE == 0) {
                if (resid) {
                    float2 q0 = *(const float2*)(resid + i0);
                    float2 q1 = *(const float2*)(resid + i1);
                    v0 += q0.x; v1 += q0.y; v2 += q1.x; v3 += q1.y;
                }
                *(float2*)(C + i0) = make_float2(v0, v1);
                *(float2*)(C + i1) = make_float2(v2, v3);
            } else {
                __half2 p0 = __floats2half2_rn(v0, v1);
                __half2 p1 = __floats2half2_rn(v2, v3);
                *(__half2*)(Ch + i0) = p0;
                *(__half2*)(Ch + i1) = p1;
            }
        }
    }
}

// ---- fused flash attention (R15 config: 128-row KV, 3-stage, 1 CTA/SM) ----
#define FA_STAGE 65536
#define FA_SMEM  (32768 + 3*FA_STAGE)
#define ONE2 0x3C003C00u

__global__ void __launch_bounds__(256, 1)
flash_attn(const h16* __restrict__ qg, const h16* __restrict__ kg,
           const h16* __restrict__ vg, const float* __restrict__ x,
           float* __restrict__ x1)
{
    extern __shared__ char smem[];
    const uint32_t smb = smem_u32(smem);
    const int qt = blockIdx.x, z = blockIdx.y;
    const int b = z >> 3, h = z & 7;
    const int tid = threadIdx.x, lane = tid & 31, wid = tid >> 5;

    const size_t qkbase = (size_t)b * Sc * Dc + (size_t)h * DKc;

    const int row = tid >> 2;
    const int cch = tid & 3;
    const int vrow = tid >> 4;
    const int vch  = tid & 15;

    {
        #pragma unroll
        for (int slab = 0; slab < 4; slab++)
            #pragma unroll
            for (int rep = 0; rep < 2; rep++) {
                const int r = row + rep * 64;
                const uint32_t so = slab * 8192 + r * 64 + ((cch ^ (r & 3)) << 4);
                CP16(smb + so, qg + qkbase + (size_t)(qt * 128 + r) * Dc + slab * 32 + cch * 8);
            }
    }
    auto load_kv = [&](int kt, int st) {
        const uint32_t sb = smb + 32768 + st * FA_STAGE;
        #pragma unroll
        for (int slab = 0; slab < 4; slab++)
            #pragma unroll
            for (int rep = 0; rep < 2; rep++) {
                const int r = row + rep * 64;
                const uint32_t so = slab * 8192 + r * 64 + ((cch ^ (r & 3)) << 4);
                CP16(sb + so, kg + qkbase + (size_t)(kt * 128 + r) * Dc + slab * 32 + cch * 8);
            }
        #pragma unroll
        for (int rep = 0; rep < 8; rep++) {
            const int r = vrow + rep * 16;
            const uint32_t so = r * 256 + ((vch ^ (r & 15)) << 4);
            CP16(sb + 32768 + so, vg + qkbase + (size_t)(kt * 128 + r) * Dc + vch * 8);
        }
        CP_COMMIT();
    };
    load_kv(0, 0);
    load_kv(1, 1);

    uint32_t aq[8][4];
    float acc_o[16][4];
    float acc_l[4] = {0.f, 0.f, 0.f, 0.f};
    #pragma unroll
    for (int nf = 0; nf < 16; nf++)
        #pragma unroll
        for (int t = 0; t < 4; t++) acc_o[nf][t] = 0.f;

    for (int kt = 0; kt < 8; kt++) {
        CP_WAIT1();
        __syncthreads();
        if (kt + 2 < 8) load_kv(kt + 2, (kt + 2) % 3);
        else CP_COMMIT();

        if (kt == 0) {
            #pragma unroll
            for (int kc = 0; kc < 8; kc++) {
                const int slab = kc >> 1, ks = kc & 1;
                const int r = wid * 16 + (lane & 15);
                const int ch = ks * 2 + (lane >> 4);
                ldsm_x4(aq[kc][0], aq[kc][1], aq[kc][2], aq[kc][3],
                        smb + slab * 8192 + r * 64 + ((ch ^ (r & 3)) << 4));
            }
        }

        const uint32_t sbk = smb + 32768 + (kt % 3) * FA_STAGE;
        const uint32_t sbv = sbk + 32768;

        float s_acc[16][4];
        #pragma unroll
        for (int nf = 0; nf < 16; nf++)
            #pragma unroll
            for (int t = 0; t < 4; t++) s_acc[nf][t] = 0.f;
        #pragma unroll
        for (int kc = 0; kc < 8; kc++) {
            const int slab = kc >> 1, ks = kc & 1;
            #pragma unroll
            for (int nf2 = 0; nf2 < 8; nf2++) {
                const int r = nf2 * 16 + ((lane >> 4) & 1) * 8 + (lane & 7);
                const int ch = ks * 2 + ((lane >> 3) & 1);
                uint32_t b0, b1, b2, b3;
                ldsm_x4(b0, b1, b2, b3, sbk + slab * 8192 + r * 64 + ((ch ^ (r & 3)) << 4));
                mma16816(s_acc[2*nf2],   aq[kc][0], aq[kc][1], aq[kc][2], aq[kc][3], b0, b1);
                mma16816(s_acc[2*nf2+1], aq[kc][0], aq[kc][1], aq[kc][2], aq[kc][3], b2, b3);
            }
        }

        #pragma unroll
        for (int kc = 0; kc < 8; kc++) {
            __half2 pa0 = __floats2half2_rn(s_acc[2*kc][0],   s_acc[2*kc][1]);
            __half2 pa1 = __floats2half2_rn(s_acc[2*kc][2],   s_acc[2*kc][3]);
            __half2 pa2 = __floats2half2_rn(s_acc[2*kc+1][0], s_acc[2*kc+1][1]);
            __half2 pa3 = __floats2half2_rn(s_acc[2*kc+1][2], s_acc[2*kc+1][3]);
            const uint32_t u0 = h2exp2_u(*(uint32_t*)&pa0);
            const uint32_t u1 = h2exp2_u(*(uint32_t*)&pa1);
            const uint32_t u2 = h2exp2_u(*(uint32_t*)&pa2);
            const uint32_t u3 = h2exp2_u(*(uint32_t*)&pa3);
            mma16816(acc_l, u0, u1, u2, u3, ONE2, ONE2);
            #pragma unroll
            for (int nf2 = 0; nf2 < 8; nf2++) {
                const int r = kc * 16 + ((lane >> 3) & 1) * 8 + (lane & 7);
                const int cb = 2 * nf2 + (lane >> 4);
                uint32_t b0, b1, b2, b3;
                ldsm_x4t(b0, b1, b2, b3, sbv + r * 256 + ((cb ^ (r & 15)) << 4));
                mma16816(acc_o[2*nf2],   u0, u1, u2, u3, b0, b1);
                mma16816(acc_o[2*nf2+1], u0, u1, u2, u3, b2, b3);
            }
        }
    }

    const float inv0 = 1.f / acc_l[0], inv1 = 1.f / acc_l[2];
    const size_t zbase = (size_t)z * Sc * DKc;
    const int gr0 = qt * 128 + wid * 16 + (lane >> 2);
    #pragma unroll
    for (int nf = 0; nf < 16; nf++) {
        const int col = nf * 8 + (lane & 3) * 2;
        const size_t i0 = zbase + (size_t)gr0 * DKc + col;
        const size_t i1 = i0 + 8 * DKc;
        float2 r0 = *(const float2*)(x + i0);
        float2 r1 = *(const float2*)(x + i1);
        *(float2*)(x1 + i0) = make_float2(acc_o[nf][0] * inv0 + r0.x, acc_o[nf][1] * inv0 + r0.y);
        *(float2*)(x1 + i1) = make_float2(acc_o[nf][2] * inv1 + r1.x, acc_o[nf][3] * inv1 + r1.y);
    }
}

// ---- layernorm -> fp16 ----
__global__ void __launch_bounds__(256)
ln_half(const float* __restrict__ x, const float* __restrict__ g,
        const float* __restrict__ b, h16* __restrict__ o)
{
    const long long row = blockIdx.x;
    const int tid = threadIdx.x;
    float4 v = *(const float4*)(x + row * Dc + tid * 4);
    float s = v.x+v.y+v.z+v.w, ss = v.x*v.x+v.y*v.y+v.z*v.z+v.w*v.w;
    __shared__ float shs[8], shq[8];
    #pragma unroll
    for (int o2 = 16; o2; o2 >>= 1) { s += __shfl_xor_sync(~0u,s,o2); ss += __shfl_xor_sync(~0u,ss,o2); }
    if ((tid & 31) == 0) { shs[tid>>5] = s; shq[tid>>5] = ss; }
    __syncthreads();
    float st=0.f, qt=0.f;
    #pragma unroll
    for (int i = 0; i < 8; i++) { st += shs[i]; qt += shq[i]; }
    const float m = st * (1.f/Dc), inv = rsqrtf(qt*(1.f/Dc) - m*m + 1e-5f);
    float4 gv = *(const float4*)(g + tid*4);
    float4 bv = *(const float4*)(b + tid*4);
    __half2 h0 = __floats2half2_rn((v.x-m)*inv*gv.x+bv.x, (v.y-m)*inv*gv.y+bv.y);
    __half2 h1 = __floats2half2_rn((v.z-m)*inv*gv.z+bv.z, (v.w-m)*inv*gv.w+bv.w);
    uint2 pk; pk.x = *(uint32_t*)&h0; pk.y = *(uint32_t*)&h1;
    *(uint2*)(o + row*Dc + tid*4) = pk;
}

// ---- merged prep: weight transposes + fold_wv + bias, ONE launch ----
__global__ void __launch_bounds__(256)
prep_all(const float* __restrict__ Wq, const float* __restrict__ Wk,
         const float* __restrict__ W1, const float* __restrict__ W2,
         const float* __restrict__ Wv,
         const float* __restrict__ bq, const float* __restrict__ bk,
         const float* __restrict__ bv,
         h16* __restrict__ oq, h16* __restrict__ ok,
         h16* __restrict__ o1, h16* __restrict__ o2,
         h16* __restrict__ ovf, float* __restrict__ bqkv)
{
    const int bid = blockIdx.x;
    const int tid = threadIdx.x;

    if (bid < 5120) {
        // transposes
        __shared__ float t[64][33];
        const float* in; h16* out;
        int ldin, ldo, tx_, ty_;
        float sc = 1.0f;
        if (bid < 512)        { int t2 = bid;        in = Wq; out = oq; ldin = Dc;  ldo = Dc;  tx_ = t2 & 31;  ty_ = t2 >> 5; sc = QSCALE; }
        else if (bid < 1024)  { int t2 = bid - 512;  in = Wk; out = ok; ldin = Dc;  ldo = Dc;  tx_ = t2 & 31;  ty_ = t2 >> 5; }
        else if (bid < 3072)  { int t2 = bid - 1024; in = W1; out = o1; ldin = FFc; ldo = Dc;  tx_ = t2 & 127; ty_ = t2 >> 7; }
        else                  { int t2 = bid - 3072; in = W2; out = o2; ldin = Dc;  ldo = FFc; tx_ = t2 & 31;  ty_ = t2 >> 5; }
        const int c0 = tx_ * 32, r0 = ty_ * 64;
        const int lcol = tid & 31, lrow = tid >> 5;
        #pragma unroll
        for (int rep = 0; rep < 8; rep++) {
            const int r = lrow + rep * 8;
            t[r][lcol] = in[(size_t)(r0 + r) * ldin + c0 + lcol];
        }
        __syncthreads();
        const int lane = tid & 31, wrp = tid >> 5;
        #pragma unroll
        for (int pass = 0; pass < 4; pass++) {
            const int c = pass * 8 + wrp;
            __half2 pk = __floats2half2_rn(t[2*lane][c] * sc, t[2*lane+1][c] * sc);
            *(__half2*)(out + (size_t)(c0 + c) * ldo + r0 + 2*lane) = pk;
        }
    } else if (bid < 6144) {
        // fold Wv [1024 x 8192] -> WvfT [1024(nf) x 1024(k)]
        __shared__ float sf[32][33];
        const int fb = bid - 5120;
        const int k0 = (fb & 31) * 32, nf0 = (fb >> 5) * 32;
        const int tx = tid & 31, ty = tid >> 5;
        #pragma unroll
        for (int rep = 0; rep < 4; rep++) {
            const int row = ty + rep * 8;
            const float* src = Wv + (size_t)(k0 + row) * (Hc*Dc) + (size_t)(nf0 + tx) * 8;
            float4 a = *(const float4*)src;
            float4 b = *(const float4*)(src + 4);
            sf[row][tx] = a.x + a.y + a.z + a.w + b.x + b.y + b.z + b.w;
        }
        __syncthreads();
        #pragma unroll
        for (int rep = 0; rep < 4; rep++) {
            const int nf = ty + rep * 8;
            ovf[(size_t)(nf0 + nf) * Dc + k0 + tx] = __float2half_rn(sf[tx][nf]);
        }
    } else {
        // bias prep
        const int i = (bid - 6144) * 256 + tid;
        bqkv[i] = bq[i] * QSCALE;
        bqkv[Dc + i] = bk[i];
        const float* s = bv + (size_t)i * 8;
        float t = 0.f;
        #pragma unroll
        for (int j = 0; j < 8; j++) t += s[j];
        bqkv[2*Dc + i] = t;
    }
}

#define SYM(p, s) cudaGetSymbolAddress((void**)&p, s)

extern "C" void kernel_launch(void* const* d_in, const int* in_sizes, int n_in,
                              void* d_out, int out_size)
{
    (void)in_sizes; (void)n_in; (void)out_size;
    const float* x   = (const float*)d_in[0];
    const float* g1  = (const float*)d_in[2];
    const float* b1  = (const float*)d_in[3];
    const float* Wq  = (const float*)d_in[4];
    const float* bq  = (const float*)d_in[5];
    const float* Wk  = (const float*)d_in[6];
    const float* bk  = (const float*)d_in[7];
    const float* Wv  = (const float*)d_in[8];
    const float* bv  = (const float*)d_in[9];
    const float* g2  = (const float*)d_in[10];
    const float* b2  = (const float*)d_in[11];
    const float* W1  = (const float*)d_in[12];
    const float* bw1 = (const float*)d_in[13];
    const float* W2  = (const float*)d_in[14];
    const float* bw2 = (const float*)d_in[15];
    float* out = (float*)d_out;

    h16 *xn,*xn2,*wqkv,*w1t,*w2t,*qkv,*ff;
    float *bqkv,*x1;
    SYM(xn,g_xn); SYM(xn2,g_xn2);
    SYM(wqkv,g_wqkv); SYM(bqkv,g_bqkv);
    SYM(w1t,g_W1T); SYM(w2t,g_W2T);
    SYM(qkv,g_qkv);
    SYM(ff,g_ff); SYM(x1,g_x1);

    cudaFuncSetAttribute(gemm_hmma<0,0>, cudaFuncAttributeMaxDynamicSharedMemorySize, GSMEM);
    cudaFuncSetAttribute(gemm_hmma<0,1>, cudaFuncAttributeMaxDynamicSharedMemorySize, GSMEM);
    cudaFuncSetAttribute(gemm_hmma<1,1>, cudaFuncAttributeMaxDynamicSharedMemorySize, GSMEM);
    cudaFuncSetAttribute(flash_attn,     cudaFuncAttributeMaxDynamicSharedMemorySize, FA_SMEM);

    const size_t DD = (size_t)Dc*Dc;

    prep_all<<<6148, 256>>>(Wq, Wk, W1, W2, Wv, bq, bk, bv,
                            wqkv, wqkv + DD, w1t, w2t, wqkv + 2*DD, bqkv);

    ln_half<<<TOK, 256>>>(x, g1, b1, xn);

    gemm_hmma<0,1><<<dim3(Dc/128, TOK/128, 3), 256, GSMEM>>>(
        xn, wqkv, bqkv, nullptr, nullptr, qkv,
        Dc, Dc, Dc, Dc,
        0, 0, (long long)DD, 0, (long long)TOK*Dc, 0, 1, 1.0f, (long long)Dc);

    flash_attn<<<dim3(Sc/128, Bc*Hc), 256, FA_SMEM>>>(
        qkv, qkv + (size_t)TOK*Dc, qkv + (size_t)2*TOK*Dc, x, x1);

    ln_half<<<TOK, 256>>>(x1, g2, b2, xn2);

    gemm_hmma<1,1><<<dim3(FFc/128, TOK/128, 1), 256, GSMEM>>>(
        xn2, w1t, bw1, nullptr, nullptr, ff,
        Dc, Dc, Dc, FFc, 0,0,0,0,0,0, 1, 1.0f, 0);

    gemm_hmma<0,0><<<dim3(Dc/128, TOK/128, 1), 256, GSMEM>>>(
        ff, w2t, bw2, x1, out, nullptr,
        FFc, FFc, FFc, Dc, 0,0,0,0,0,0, 1, 1.0f, 0);
}